// round 4
// baseline (speedup 1.0000x reference)
#include <cuda_runtime.h>
#include <math_constants.h>

// Problem constants
#define Bb 2
#define Ss 4096
#define Hh 8
#define HDv 512   // H*D (D=64)

typedef unsigned long long ull;

// Scratch (device globals; no allocation allowed)
__device__ float Qg[Bb * Ss * HDv];
__device__ float Kg[Bb * Ss * HDv];
__device__ float Vg[Bb * Ss * HDv];
__device__ float Og[Bb * Ss * HDv];

// ---- packed f32x2 helpers -------------------------------------------------
__device__ __forceinline__ ull pk2(float a, float b) {
    ull r; asm("mov.b64 %0, {%1, %2};" : "=l"(r) : "f"(a), "f"(b)); return r;
}
__device__ __forceinline__ void upk(ull v, float& a, float& b) {
    asm("mov.b64 {%0, %1}, %2;" : "=f"(a), "=f"(b) : "l"(v));
}
__device__ __forceinline__ ull f2fma(ull a, ull b, ull c) {
    ull d; asm("fma.rn.f32x2 %0, %1, %2, %3;" : "=l"(d) : "l"(a), "l"(b), "l"(c));
    return d;
}
__device__ __forceinline__ ull f2mul(ull a, ull b) {
    ull d; asm("mul.rn.f32x2 %0, %1, %2;" : "=l"(d) : "l"(a), "l"(b));
    return d;
}

// ---------------------------------------------------------------------------
// SGEMM: C[M,512] = A[M,512] @ B[512,512], M multiple of 128. (unchanged)
// ---------------------------------------------------------------------------
__global__ __launch_bounds__(256) void sgemm_k512(
    const float* __restrict__ A, const float* __restrict__ Bw,
    float* __restrict__ C)
{
    __shared__ float As[8][128];
    __shared__ float Bs[8][128];

    const int tid = threadIdx.x;
    const int tx = tid & 15;
    const int ty = tid >> 4;
    const int bn = blockIdx.x * 128;
    const int bm = blockIdx.y * 128;

    const int arow = tid >> 1;
    const int acol = (tid & 1) << 2;
    const int brow = tid >> 5;
    const int bcol = (tid & 31) << 2;

    const float* Ap = A + (size_t)(bm + arow) * 512 + acol;
    const float* Bp = Bw + (size_t)brow * 512 + bn + bcol;

    ull acc2[8][4];
#pragma unroll
    for (int i = 0; i < 8; ++i)
#pragma unroll
        for (int j = 0; j < 4; ++j) acc2[i][j] = 0ull;

    for (int k0 = 0; k0 < 512; k0 += 8) {
        float4 av = *(const float4*)Ap;  Ap += 8;
        float4 bv = *(const float4*)Bp;  Bp += 8 * 512;
        As[acol + 0][arow] = av.x;
        As[acol + 1][arow] = av.y;
        As[acol + 2][arow] = av.z;
        As[acol + 3][arow] = av.w;
        *(float4*)&Bs[brow][bcol] = bv;
        __syncthreads();
#pragma unroll
        for (int kk = 0; kk < 8; ++kk) {
            float ar[8];
            *(float4*)(ar)     = *(const float4*)&As[kk][ty * 8];
            *(float4*)(ar + 4) = *(const float4*)&As[kk][ty * 8 + 4];
            ulonglong2 b01 = *(const ulonglong2*)&Bs[kk][tx * 8];
            ulonglong2 b23 = *(const ulonglong2*)&Bs[kk][tx * 8 + 4];
#pragma unroll
            for (int i = 0; i < 8; ++i) {
                ull ap = pk2(ar[i], ar[i]);
                acc2[i][0] = f2fma(ap, b01.x, acc2[i][0]);
                acc2[i][1] = f2fma(ap, b01.y, acc2[i][1]);
                acc2[i][2] = f2fma(ap, b23.x, acc2[i][2]);
                acc2[i][3] = f2fma(ap, b23.y, acc2[i][3]);
            }
        }
        __syncthreads();
    }

    float* Cp = C + (size_t)(bm + ty * 8) * 512 + bn + tx * 8;
#pragma unroll
    for (int i = 0; i < 8; ++i) {
        float c0, c1, c2, c3, c4, c5, c6, c7;
        upk(acc2[i][0], c0, c1); upk(acc2[i][1], c2, c3);
        upk(acc2[i][2], c4, c5); upk(acc2[i][3], c6, c7);
        *(float4*)(Cp + (size_t)i * 512)     = make_float4(c0, c1, c2, c3);
        *(float4*)(Cp + (size_t)i * 512 + 4) = make_float4(c4, c5, c6, c7);
    }
}

// ---------------------------------------------------------------------------
// Flash attention v3: contraction-packed FFMA2.
// One block per (b, h, 64-row q tile). 256 threads, 4q x 4k per thread.
// FFMA2 lanes hold (even,odd) partial sums along the CONTRACTED dim; collapsed
// lo+hi after each GEMM. All smem tiles natural row-major except V (stored
// transposed [d][k] so PV pairs along k are contiguous).
// smem 48 KB: Qs[64][64] [q][d] | KVs[64][64] (K:[k][d], then V:[d][k]) |
//             Ps[64][64] [q][k]
// ---------------------------------------------------------------------------
__global__ void __launch_bounds__(256, 2) flash_attn(
    const float* __restrict__ Q, const float* __restrict__ K,
    const float* __restrict__ V, const int* __restrict__ Mask,
    float* __restrict__ O)
{
    extern __shared__ float dsm[];
    float* Qs  = dsm;             // [q][d]
    float* KVs = dsm + 4096;      // K: [k][d]  /  V: [d][k]
    float* Ps  = dsm + 8192;      // [q][k]

    const int tid = threadIdx.x;
    const int tx = tid & 15;      // 4 cols: 4*tx+j
    const int ty = tid >> 4;      // 4 rows: 4*ty+i
    const int q0 = blockIdx.x * 64;
    const int h  = blockIdx.y;
    const int b  = blockIdx.z;

    const int row  = tid >> 2;    // 0..63 cooperative-load row
    const int quad = tid & 3;     // 16-float column group

    // Load Q tile natural [q][d]
    {
        const float* qp = Q + (size_t)(b * Ss + q0 + row) * HDv + h * 64 + quad * 16;
#pragma unroll
        for (int i = 0; i < 4; ++i)
            *(float4*)&Qs[row * 64 + quad * 16 + 4 * i] = *(const float4*)(qp + 4 * i);
    }

    float m_i[4], l_i[4];
    ull acc2[4][4];               // pairs over k; O = lo+hi at the end
#pragma unroll
    for (int i = 0; i < 4; ++i) {
        m_i[i] = -CUDART_INF_F;
        l_i[i] = 0.f;
#pragma unroll
        for (int j = 0; j < 4; ++j) acc2[i][j] = 0ull;
    }

    const int* mbase = Mask + ((size_t)(b * Hh + h) * Ss + q0) * Ss;

    for (int k0 = 0; k0 < Ss; k0 += 64) {
        __syncthreads();  // prior PV reads of KVs/Ps done (covers Q store, iter 0)

        // Load K tile natural [k][d]
        {
            const float* kp = K + (size_t)(b * Ss + k0 + row) * HDv + h * 64 + quad * 16;
#pragma unroll
            for (int i = 0; i < 4; ++i)
                *(float4*)&KVs[row * 64 + quad * 16 + 4 * i] = *(const float4*)(kp + 4 * i);
        }
        __syncthreads();

        // ---- S = Q K^T : pairs along d ----
        ull s2[4][4];
#pragma unroll
        for (int i = 0; i < 4; ++i)
#pragma unroll
            for (int j = 0; j < 4; ++j) s2[i][j] = 0ull;

#pragma unroll 4
        for (int dc = 0; dc < 16; ++dc) {
            ulonglong2 q2[4], k2[4];
#pragma unroll
            for (int i = 0; i < 4; ++i)
                q2[i] = *(const ulonglong2*)&Qs[(4 * ty + i) * 64 + 4 * dc];
#pragma unroll
            for (int j = 0; j < 4; ++j)
                k2[j] = *(const ulonglong2*)&KVs[(4 * tx + j) * 64 + 4 * dc];
#pragma unroll
            for (int i = 0; i < 4; ++i)
#pragma unroll
                for (int j = 0; j < 4; ++j) {
                    s2[i][j] = f2fma(q2[i].x, k2[j].x, s2[i][j]);
                    s2[i][j] = f2fma(q2[i].y, k2[j].y, s2[i][j]);
                }
        }

        // Mask loads (direct LDG.128, batched for MLP)
        int4 mreg[4];
#pragma unroll
        for (int i = 0; i < 4; ++i)
            mreg[i] = *(const int4*)(mbase + (size_t)(4 * ty + i) * Ss + k0 + 4 * tx);

        // ---- online softmax, write P natural [q][k] ----
#pragma unroll
        for (int i = 0; i < 4; ++i) {
            float a0, b0, a1, b1, a2, b2, a3, b3;
            upk(s2[i][0], a0, b0); upk(s2[i][1], a1, b1);
            upk(s2[i][2], a2, b2); upk(s2[i][3], a3, b3);
            float s0 = a0 + b0, s1 = a1 + b1, sv = a2 + b2, s3 = a3 + b3;
            s0 = (mreg[i].x != 0) ? -1e10f : s0 * 0.125f;
            s1 = (mreg[i].y != 0) ? -1e10f : s1 * 0.125f;
            sv = (mreg[i].z != 0) ? -1e10f : sv * 0.125f;
            s3 = (mreg[i].w != 0) ? -1e10f : s3 * 0.125f;

            float mt = fmaxf(fmaxf(s0, s1), fmaxf(sv, s3));
#pragma unroll
            for (int off = 8; off; off >>= 1)
                mt = fmaxf(mt, __shfl_xor_sync(0xffffffffu, mt, off));
            float mnew = fmaxf(m_i[i], mt);
            float corr = __expf(m_i[i] - mnew);
            m_i[i] = mnew;

            float p0 = __expf(s0 - mnew);
            float p1 = __expf(s1 - mnew);
            float p2 = __expf(sv - mnew);
            float p3 = __expf(s3 - mnew);
            float rs = (p0 + p1) + (p2 + p3);
#pragma unroll
            for (int off = 8; off; off >>= 1)
                rs += __shfl_xor_sync(0xffffffffu, rs, off);
            l_i[i] = l_i[i] * corr + rs;

            ull c2 = pk2(corr, corr);
#pragma unroll
            for (int j = 0; j < 4; ++j) acc2[i][j] = f2mul(acc2[i][j], c2);

            *(float4*)&Ps[(4 * ty + i) * 64 + 4 * tx] = make_float4(p0, p1, p2, p3);
        }

        __syncthreads();  // QK reads of KVs done -> reuse for V

        // Load V tile TRANSPOSED: KVs[d][k]
        {
            const float* vp = V + (size_t)(b * Ss + k0 + row) * HDv + h * 64 + quad * 16;
#pragma unroll
            for (int i = 0; i < 4; ++i) {
                float4 v = *(const float4*)(vp + 4 * i);
                int d = quad * 16 + 4 * i;
                KVs[(d + 0) * 64 + row] = v.x;
                KVs[(d + 1) * 64 + row] = v.y;
                KVs[(d + 2) * 64 + row] = v.z;
                KVs[(d + 3) * 64 + row] = v.w;
            }
        }
        __syncthreads();  // V + P visible

        // ---- O += P V : pairs along k ----
#pragma unroll 4
        for (int kc = 0; kc < 16; ++kc) {
            ulonglong2 p2[4], v2[4];
#pragma unroll
            for (int i = 0; i < 4; ++i)
                p2[i] = *(const ulonglong2*)&Ps[(4 * ty + i) * 64 + 4 * kc];
#pragma unroll
            for (int j = 0; j < 4; ++j)
                v2[j] = *(const ulonglong2*)&KVs[(4 * tx + j) * 64 + 4 * kc];
#pragma unroll
            for (int i = 0; i < 4; ++i)
#pragma unroll
                for (int j = 0; j < 4; ++j) {
                    acc2[i][j] = f2fma(p2[i].x, v2[j].x, acc2[i][j]);
                    acc2[i][j] = f2fma(p2[i].y, v2[j].y, acc2[i][j]);
                }
        }
    }

    // collapse pairs, normalize, write
#pragma unroll
    for (int i = 0; i < 4; ++i) {
        float inv = 1.f / l_i[i];
        float o[4];
#pragma unroll
        for (int j = 0; j < 4; ++j) {
            float lo, hi;
            upk(acc2[i][j], lo, hi);
            o[j] = (lo + hi) * inv;
        }
        *(float4*)&O[(size_t)(b * Ss + q0 + 4 * ty + i) * HDv + h * 64 + 4 * tx] =
            make_float4(o[0], o[1], o[2], o[3]);
    }
}

// ---------------------------------------------------------------------------
// Launch
// ---------------------------------------------------------------------------
extern "C" void kernel_launch(void* const* d_in, const int* in_sizes, int n_in,
                              void* d_out, int out_size)
{
    (void)in_sizes; (void)n_in; (void)out_size;
    const float* queries = (const float*)d_in[0];
    const float* keys    = (const float*)d_in[1];
    const float* values  = (const float*)d_in[2];
    const int*   mask    = (const int*)d_in[3];
    const float* Wq = (const float*)d_in[4];
    const float* Wk = (const float*)d_in[5];
    const float* Wv = (const float*)d_in[6];
    const float* Wo = (const float*)d_in[7];

    void *qp, *kp, *vp, *op;
    cudaGetSymbolAddress(&qp, Qg);
    cudaGetSymbolAddress(&kp, Kg);
    cudaGetSymbolAddress(&vp, Vg);
    cudaGetSymbolAddress(&op, Og);

    cudaFuncSetAttribute(flash_attn,
                         cudaFuncAttributeMaxDynamicSharedMemorySize, 49152);

    dim3 gg(512 / 128, (Bb * Ss) / 128);  // (4, 64)
    dim3 gt(256);

    sgemm_k512<<<gg, gt>>>(queries, Wq, (float*)qp);
    sgemm_k512<<<gg, gt>>>(keys,    Wk, (float*)kp);
    sgemm_k512<<<gg, gt>>>(values,  Wv, (float*)vp);

    flash_attn<<<dim3(Ss / 64, Hh, Bb), 256, 49152>>>(
        (const float*)qp, (const float*)kp, (const float*)vp, mask, (float*)op);

    sgemm_k512<<<gg, gt>>>((const float*)op, Wo, (float*)d_out);
}

// round 5
// speedup vs baseline: 5.5267x; 5.5267x over previous
#include <cuda_runtime.h>
#include <math_constants.h>

// Problem constants
#define Bb 2
#define Ss 4096
#define Hh 8
#define HDv 512   // H*D (D=64)

typedef unsigned long long ull;
typedef unsigned int u32;

// Scratch (device globals; no allocation allowed)
__device__ float Qg[Bb * Ss * HDv];
__device__ float Kg[Bb * Ss * HDv];
__device__ float Vg[Bb * Ss * HDv];
__device__ float Og[Bb * Ss * HDv];

// ---- helpers --------------------------------------------------------------
__device__ __forceinline__ ull pk2(float a, float b) {
    ull r; asm("mov.b64 %0, {%1, %2};" : "=l"(r) : "f"(a), "f"(b)); return r;
}
__device__ __forceinline__ void upk(ull v, float& a, float& b) {
    asm("mov.b64 {%0, %1}, %2;" : "=f"(a), "=f"(b) : "l"(v));
}
__device__ __forceinline__ ull f2fma(ull a, ull b, ull c) {
    ull d; asm("fma.rn.f32x2 %0, %1, %2, %3;" : "=l"(d) : "l"(a), "l"(b), "l"(c));
    return d;
}
__device__ __forceinline__ u32 to_tf32(float f) {
    u32 r; asm("cvt.rna.tf32.f32 %0, %1;" : "=r"(r) : "f"(f)); return r;
}
__device__ __forceinline__ void mma_tf32(
    float& d0, float& d1, float& d2, float& d3,
    u32 a0, u32 a1, u32 a2, u32 a3, u32 b0, u32 b1)
{
    asm("mma.sync.aligned.m16n8k8.row.col.f32.tf32.tf32.f32 "
        "{%0,%1,%2,%3}, {%4,%5,%6,%7}, {%8,%9}, {%0,%1,%2,%3};"
        : "+f"(d0), "+f"(d1), "+f"(d2), "+f"(d3)
        : "r"(a0), "r"(a1), "r"(a2), "r"(a3), "r"(b0), "r"(b1));
}

// ---------------------------------------------------------------------------
// SGEMM: C[M,512] = A[M,512] @ B[512,512] (fp32 FFMA2, unchanged / proven)
// ---------------------------------------------------------------------------
__global__ __launch_bounds__(256) void sgemm_k512(
    const float* __restrict__ A, const float* __restrict__ Bw,
    float* __restrict__ C)
{
    __shared__ float As[8][128];
    __shared__ float Bs[8][128];

    const int tid = threadIdx.x;
    const int tx = tid & 15;
    const int ty = tid >> 4;
    const int bn = blockIdx.x * 128;
    const int bm = blockIdx.y * 128;

    const int arow = tid >> 1;
    const int acol = (tid & 1) << 2;
    const int brow = tid >> 5;
    const int bcol = (tid & 31) << 2;

    const float* Ap = A + (size_t)(bm + arow) * 512 + acol;
    const float* Bp = Bw + (size_t)brow * 512 + bn + bcol;

    ull acc2[8][4];
#pragma unroll
    for (int i = 0; i < 8; ++i)
#pragma unroll
        for (int j = 0; j < 4; ++j) acc2[i][j] = 0ull;

    for (int k0 = 0; k0 < 512; k0 += 8) {
        float4 av = *(const float4*)Ap;  Ap += 8;
        float4 bv = *(const float4*)Bp;  Bp += 8 * 512;
        As[acol + 0][arow] = av.x;
        As[acol + 1][arow] = av.y;
        As[acol + 2][arow] = av.z;
        As[acol + 3][arow] = av.w;
        *(float4*)&Bs[brow][bcol] = bv;
        __syncthreads();
#pragma unroll
        for (int kk = 0; kk < 8; ++kk) {
            float ar[8];
            *(float4*)(ar)     = *(const float4*)&As[kk][ty * 8];
            *(float4*)(ar + 4) = *(const float4*)&As[kk][ty * 8 + 4];
            ulonglong2 b01 = *(const ulonglong2*)&Bs[kk][tx * 8];
            ulonglong2 b23 = *(const ulonglong2*)&Bs[kk][tx * 8 + 4];
#pragma unroll
            for (int i = 0; i < 8; ++i) {
                ull ap = pk2(ar[i], ar[i]);
                acc2[i][0] = f2fma(ap, b01.x, acc2[i][0]);
                acc2[i][1] = f2fma(ap, b01.y, acc2[i][1]);
                acc2[i][2] = f2fma(ap, b23.x, acc2[i][2]);
                acc2[i][3] = f2fma(ap, b23.y, acc2[i][3]);
            }
        }
        __syncthreads();
    }

    float* Cp = C + (size_t)(bm + ty * 8) * 512 + bn + tx * 8;
#pragma unroll
    for (int i = 0; i < 8; ++i) {
        float c0, c1, c2, c3, c4, c5, c6, c7;
        upk(acc2[i][0], c0, c1); upk(acc2[i][1], c2, c3);
        upk(acc2[i][2], c4, c5); upk(acc2[i][3], c6, c7);
        *(float4*)(Cp + (size_t)i * 512)     = make_float4(c0, c1, c2, c3);
        *(float4*)(Cp + (size_t)i * 512 + 4) = make_float4(c4, c5, c6, c7);
    }
}

// ---------------------------------------------------------------------------
// Flash attention v4: tf32 mma.sync (m16n8k8), fp32 accumulate.
// One block per (b, h, 64-row q tile). 128 threads = 4 warps x 16 q-rows.
// smem (stride 68 floats per row -> all fragment LDS conflict-free):
//   Qs [64][68] tf32 bits, [q][d]
//   Ks [64][68]           K: [k][d]  then  Vt: [d][k]  (reused)
//   Ps [64][68]           P: [q][k] tf32 bits
// Total = 3 * 64*68*4 = 52224 B.
// Fragment maps (m16n8k8.tf32, g=lane>>2, c=lane&3):
//   A: a0(g,c) a1(g+8,c) a2(g,c+4) a3(g+8,c+4)
//   B: b0(k=c,n=g) b1(k=c+4,n=g)
//   D: d0(g,2c) d1(g,2c+1) d2(g+8,2c) d3(g+8,2c+1)
// ---------------------------------------------------------------------------
#define LDW 68

__global__ void __launch_bounds__(128, 4) flash_attn(
    const float* __restrict__ Q, const float* __restrict__ K,
    const float* __restrict__ V, const int* __restrict__ Mask,
    float* __restrict__ O)
{
    extern __shared__ u32 dsm[];
    u32* Qs = dsm;                  // [64][LDW]
    u32* Ks = dsm + 64 * LDW;       // K then Vt
    u32* Ps = dsm + 2 * 64 * LDW;   // [64][LDW]

    const int tid  = threadIdx.x;
    const int lane = tid & 31;
    const int w    = tid >> 5;       // warp 0..3 -> q rows [16w, 16w+16)
    const int g    = lane >> 2;      // 0..7
    const int c    = lane & 3;       // 0..3
    const int q0 = blockIdx.x * 64;
    const int h  = blockIdx.y;
    const int b  = blockIdx.z;

    const int row  = tid >> 1;          // 0..63 coop-load row
    const int half = (tid & 1) * 32;    // 32-float half

    // Load Q tile -> tf32 bits, natural [q][d]
    {
        const float* qp = Q + (size_t)(b * Ss + q0 + row) * HDv + h * 64 + half;
#pragma unroll
        for (int i = 0; i < 8; ++i) {
            float4 v = *(const float4*)(qp + 4 * i);
            uint4 t = make_uint4(to_tf32(v.x), to_tf32(v.y), to_tf32(v.z), to_tf32(v.w));
            *(uint4*)&Qs[row * LDW + half + 4 * i] = t;
        }
    }

    float m0 = -CUDART_INF_F, m1 = -CUDART_INF_F, l0 = 0.f, l1 = 0.f;
    float o[8][4];
#pragma unroll
    for (int nt = 0; nt < 8; ++nt)
#pragma unroll
        for (int j = 0; j < 4; ++j) o[nt][j] = 0.f;

    const int* mrow0 = Mask + ((size_t)(b * Hh + h) * Ss + q0 + 16 * w + g) * Ss;
    const int* mrow1 = mrow0 + (size_t)8 * Ss;

    const int aQ0 = (16 * w + g) * LDW + c;       // Qs a0 base (add ks*8)
    const int aQ1 = aQ0 + 8 * LDW;
    const int aP0 = aQ0;                           // Ps uses same rows
    const int aP1 = aQ1;

    for (int k0 = 0; k0 < Ss; k0 += 64) {
        __syncthreads();  // prior PV reads of Ks/Ps done (covers Q store, iter 0)

        // K tile -> tf32 bits, natural [k][d]
        {
            const float* kp = K + (size_t)(b * Ss + k0 + row) * HDv + h * 64 + half;
#pragma unroll
            for (int i = 0; i < 8; ++i) {
                float4 v = *(const float4*)(kp + 4 * i);
                uint4 t = make_uint4(to_tf32(v.x), to_tf32(v.y), to_tf32(v.z), to_tf32(v.w));
                *(uint4*)&Ks[row * LDW + half + 4 * i] = t;
            }
        }
        __syncthreads();

        // ---- S = Q K^T ----
        float s[8][4];
#pragma unroll
        for (int nt = 0; nt < 8; ++nt)
#pragma unroll
            for (int j = 0; j < 4; ++j) s[nt][j] = 0.f;

#pragma unroll
        for (int ks = 0; ks < 8; ++ks) {
            u32 a0 = Qs[aQ0 + ks * 8];
            u32 a1 = Qs[aQ1 + ks * 8];
            u32 a2 = Qs[aQ0 + ks * 8 + 4];
            u32 a3 = Qs[aQ1 + ks * 8 + 4];
#pragma unroll
            for (int nt = 0; nt < 8; ++nt) {
                u32 b0 = Ks[(nt * 8 + g) * LDW + ks * 8 + c];
                u32 b1 = Ks[(nt * 8 + g) * LDW + ks * 8 + c + 4];
                mma_tf32(s[nt][0], s[nt][1], s[nt][2], s[nt][3],
                         a0, a1, a2, a3, b0, b1);
            }
        }

        // ---- row 0 (q = g): mask, online softmax, P store ----
        {
            int2 mr[8];
#pragma unroll
            for (int nt = 0; nt < 8; ++nt)
                mr[nt] = *(const int2*)(mrow0 + k0 + nt * 8 + 2 * c);
            float mt = -CUDART_INF_F;
#pragma unroll
            for (int nt = 0; nt < 8; ++nt) {
                s[nt][0] = (mr[nt].x != 0) ? -1e10f : s[nt][0] * 0.125f;
                s[nt][1] = (mr[nt].y != 0) ? -1e10f : s[nt][1] * 0.125f;
                mt = fmaxf(mt, fmaxf(s[nt][0], s[nt][1]));
            }
            mt = fmaxf(mt, __shfl_xor_sync(0xffffffffu, mt, 1));
            mt = fmaxf(mt, __shfl_xor_sync(0xffffffffu, mt, 2));
            float mnew = fmaxf(m0, mt);
            float corr = __expf(m0 - mnew);
            m0 = mnew;
            float rs = 0.f;
#pragma unroll
            for (int nt = 0; nt < 8; ++nt) {
                float p0 = __expf(s[nt][0] - mnew);
                float p1 = __expf(s[nt][1] - mnew);
                rs += p0 + p1;
                *(uint2*)&Ps[aP0 - c + nt * 8 + 2 * c] =
                    make_uint2(to_tf32(p0), to_tf32(p1));
                o[nt][0] *= corr;
                o[nt][1] *= corr;
            }
            rs += __shfl_xor_sync(0xffffffffu, rs, 1);
            rs += __shfl_xor_sync(0xffffffffu, rs, 2);
            l0 = l0 * corr + rs;
        }
        // ---- row 1 (q = g+8) ----
        {
            int2 mr[8];
#pragma unroll
            for (int nt = 0; nt < 8; ++nt)
                mr[nt] = *(const int2*)(mrow1 + k0 + nt * 8 + 2 * c);
            float mt = -CUDART_INF_F;
#pragma unroll
            for (int nt = 0; nt < 8; ++nt) {
                s[nt][2] = (mr[nt].x != 0) ? -1e10f : s[nt][2] * 0.125f;
                s[nt][3] = (mr[nt].y != 0) ? -1e10f : s[nt][3] * 0.125f;
                mt = fmaxf(mt, fmaxf(s[nt][2], s[nt][3]));
            }
            mt = fmaxf(mt, __shfl_xor_sync(0xffffffffu, mt, 1));
            mt = fmaxf(mt, __shfl_xor_sync(0xffffffffu, mt, 2));
            float mnew = fmaxf(m1, mt);
            float corr = __expf(m1 - mnew);
            m1 = mnew;
            float rs = 0.f;
#pragma unroll
            for (int nt = 0; nt < 8; ++nt) {
                float p0 = __expf(s[nt][2] - mnew);
                float p1 = __expf(s[nt][3] - mnew);
                rs += p0 + p1;
                *(uint2*)&Ps[aP1 - c + nt * 8 + 2 * c] =
                    make_uint2(to_tf32(p0), to_tf32(p1));
                o[nt][2] *= corr;
                o[nt][3] *= corr;
            }
            rs += __shfl_xor_sync(0xffffffffu, rs, 1);
            rs += __shfl_xor_sync(0xffffffffu, rs, 2);
            l1 = l1 * corr + rs;
        }

        __syncthreads();  // QK reads of Ks done -> overwrite with Vt

        // V tile -> tf32 bits, TRANSPOSED [d][k]
        {
            const float* vp = V + (size_t)(b * Ss + k0 + row) * HDv + h * 64 + half;
#pragma unroll
            for (int i = 0; i < 8; ++i) {
                float4 v = *(const float4*)(vp + 4 * i);
                int d = half + 4 * i;
                Ks[(d + 0) * LDW + row] = to_tf32(v.x);
                Ks[(d + 1) * LDW + row] = to_tf32(v.y);
                Ks[(d + 2) * LDW + row] = to_tf32(v.z);
                Ks[(d + 3) * LDW + row] = to_tf32(v.w);
            }
        }
        __syncthreads();  // Vt + P visible

        // ---- O += P V ----
#pragma unroll
        for (int kc = 0; kc < 8; ++kc) {
            u32 a0 = Ps[aP0 + kc * 8];
            u32 a1 = Ps[aP1 + kc * 8];
            u32 a2 = Ps[aP0 + kc * 8 + 4];
            u32 a3 = Ps[aP1 + kc * 8 + 4];
#pragma unroll
            for (int nt = 0; nt < 8; ++nt) {
                u32 b0 = Ks[(nt * 8 + g) * LDW + kc * 8 + c];
                u32 b1 = Ks[(nt * 8 + g) * LDW + kc * 8 + c + 4];
                mma_tf32(o[nt][0], o[nt][1], o[nt][2], o[nt][3],
                         a0, a1, a2, a3, b0, b1);
            }
        }
    }

    // normalize + write
    const float inv0 = 1.f / l0;
    const float inv1 = 1.f / l1;
    float* op0 = O + (size_t)(b * Ss + q0 + 16 * w + g) * HDv + h * 64;
    float* op1 = op0 + (size_t)8 * HDv;
#pragma unroll
    for (int nt = 0; nt < 8; ++nt) {
        *(float2*)(op0 + nt * 8 + 2 * c) = make_float2(o[nt][0] * inv0, o[nt][1] * inv0);
        *(float2*)(op1 + nt * 8 + 2 * c) = make_float2(o[nt][2] * inv1, o[nt][3] * inv1);
    }
}

// ---------------------------------------------------------------------------
// Launch
// ---------------------------------------------------------------------------
extern "C" void kernel_launch(void* const* d_in, const int* in_sizes, int n_in,
                              void* d_out, int out_size)
{
    (void)in_sizes; (void)n_in; (void)out_size;
    const float* queries = (const float*)d_in[0];
    const float* keys    = (const float*)d_in[1];
    const float* values  = (const float*)d_in[2];
    const int*   mask    = (const int*)d_in[3];
    const float* Wq = (const float*)d_in[4];
    const float* Wk = (const float*)d_in[5];
    const float* Wv = (const float*)d_in[6];
    const float* Wo = (const float*)d_in[7];

    void *qp, *kp, *vp, *op;
    cudaGetSymbolAddress(&qp, Qg);
    cudaGetSymbolAddress(&kp, Kg);
    cudaGetSymbolAddress(&vp, Vg);
    cudaGetSymbolAddress(&op, Og);

    const int smem = 3 * 64 * LDW * 4;  // 52224
    cudaFuncSetAttribute(flash_attn,
                         cudaFuncAttributeMaxDynamicSharedMemorySize, smem);

    dim3 gg(512 / 128, (Bb * Ss) / 128);  // (4, 64)
    dim3 gt(256);

    sgemm_k512<<<gg, gt>>>(queries, Wq, (float*)qp);
    sgemm_k512<<<gg, gt>>>(keys,    Wk, (float*)kp);
    sgemm_k512<<<gg, gt>>>(values,  Wv, (float*)vp);

    flash_attn<<<dim3(Ss / 64, Hh, Bb), 128, smem>>>(
        (const float*)qp, (const float*)kp, (const float*)vp, mask, (float*)op);

    sgemm_k512<<<gg, gt>>>((const float*)op, Wo, (float*)d_out);
}

// round 6
// speedup vs baseline: 6.6759x; 1.2079x over previous
#include <cuda_runtime.h>
#include <math_constants.h>

// Problem constants
#define Bb 2
#define Ss 4096
#define Hh 8
#define HDv 512   // H*D (D=64)

typedef unsigned long long ull;
typedef unsigned int u32;

// Scratch (device globals; no allocation allowed)
__device__ float Qg[Bb * Ss * HDv];
__device__ float Kg[Bb * Ss * HDv];
__device__ float Vg[Bb * Ss * HDv];
__device__ float Og[Bb * Ss * HDv];

// ---- helpers --------------------------------------------------------------
__device__ __forceinline__ ull pk2(float a, float b) {
    ull r; asm("mov.b64 %0, {%1, %2};" : "=l"(r) : "f"(a), "f"(b)); return r;
}
__device__ __forceinline__ void upk(ull v, float& a, float& b) {
    asm("mov.b64 {%0, %1}, %2;" : "=f"(a), "=f"(b) : "l"(v));
}
__device__ __forceinline__ ull f2fma(ull a, ull b, ull c) {
    ull d; asm("fma.rn.f32x2 %0, %1, %2, %3;" : "=l"(d) : "l"(a), "l"(b), "l"(c));
    return d;
}
__device__ __forceinline__ u32 to_tf32(float f) {
    u32 r; asm("cvt.rna.tf32.f32 %0, %1;" : "=r"(r) : "f"(f)); return r;
}
__device__ __forceinline__ void mma_tf32(
    float& d0, float& d1, float& d2, float& d3,
    u32 a0, u32 a1, u32 a2, u32 a3, u32 b0, u32 b1)
{
    asm("mma.sync.aligned.m16n8k8.row.col.f32.tf32.tf32.f32 "
        "{%0,%1,%2,%3}, {%4,%5,%6,%7}, {%8,%9}, {%0,%1,%2,%3};"
        : "+f"(d0), "+f"(d1), "+f"(d2), "+f"(d3)
        : "r"(a0), "r"(a1), "r"(a2), "r"(a3), "r"(b0), "r"(b1));
}

// ---------------------------------------------------------------------------
// tf32 GEMM for projections: C[M,512] = A[M,512] @ B[512,512].
// CTA 128x128, BK=32, 256 threads = 8 warps (4 m-groups x 2 n-groups),
// warp tile m32 x n64. smem: As[128][36] tf32 [m][k], Bs[32][136] tf32 [k][n].
// Fragment bank checks: A 4g+c, B 8c+g -> conflict-free.
// ---------------------------------------------------------------------------
#define LDA 36
#define LDB 136

__global__ __launch_bounds__(256) void gemm_tf32_k512(
    const float* __restrict__ A, const float* __restrict__ Bw,
    float* __restrict__ C)
{
    __shared__ u32 As[128 * LDA];   // 18432 B
    __shared__ u32 Bs[32 * LDB];    // 17408 B

    const int tid  = threadIdx.x;
    const int lane = tid & 31;
    const int w    = tid >> 5;
    const int g    = lane >> 2;
    const int c    = lane & 3;
    const int wm   = w & 3;         // m group (32 rows)
    const int wn   = w >> 2;        // n group (64 cols)
    const int bn = blockIdx.x * 128;
    const int bm = blockIdx.y * 128;

    const int arow = tid >> 1;              // 0..127
    const int akg  = (tid & 1) * 16;
    const int brow = tid >> 3;              // 0..31
    const int bcg  = (tid & 7) * 16;

    float acc[2][8][4];
#pragma unroll
    for (int mt = 0; mt < 2; ++mt)
#pragma unroll
        for (int nt = 0; nt < 8; ++nt)
#pragma unroll
            for (int j = 0; j < 4; ++j) acc[mt][nt][j] = 0.f;

    for (int k0 = 0; k0 < 512; k0 += 32) {
        // A tile [128][32]
        {
            const float* Ap = A + (size_t)(bm + arow) * 512 + k0 + akg;
#pragma unroll
            for (int i = 0; i < 4; ++i) {
                float4 v = *(const float4*)(Ap + 4 * i);
                *(uint4*)&As[arow * LDA + akg + 4 * i] =
                    make_uint4(to_tf32(v.x), to_tf32(v.y), to_tf32(v.z), to_tf32(v.w));
            }
        }
        // B tile [32][128]
        {
            const float* Bp = Bw + (size_t)(k0 + brow) * 512 + bn + bcg;
#pragma unroll
            for (int i = 0; i < 4; ++i) {
                float4 v = *(const float4*)(Bp + 4 * i);
                *(uint4*)&Bs[brow * LDB + bcg + 4 * i] =
                    make_uint4(to_tf32(v.x), to_tf32(v.y), to_tf32(v.z), to_tf32(v.w));
            }
        }
        __syncthreads();

#pragma unroll
        for (int ks = 0; ks < 4; ++ks) {
            u32 a[2][4];
#pragma unroll
            for (int mt = 0; mt < 2; ++mt) {
                int base = (32 * wm + 16 * mt + g) * LDA + ks * 8 + c;
                a[mt][0] = As[base];
                a[mt][1] = As[base + 8 * LDA];
                a[mt][2] = As[base + 4];
                a[mt][3] = As[base + 8 * LDA + 4];
            }
#pragma unroll
            for (int nt = 0; nt < 8; ++nt) {
                u32 b0 = Bs[(ks * 8 + c)     * LDB + 64 * wn + nt * 8 + g];
                u32 b1 = Bs[(ks * 8 + c + 4) * LDB + 64 * wn + nt * 8 + g];
#pragma unroll
                for (int mt = 0; mt < 2; ++mt)
                    mma_tf32(acc[mt][nt][0], acc[mt][nt][1], acc[mt][nt][2], acc[mt][nt][3],
                             a[mt][0], a[mt][1], a[mt][2], a[mt][3], b0, b1);
            }
        }
        __syncthreads();
    }

#pragma unroll
    for (int mt = 0; mt < 2; ++mt) {
        float* Cp0 = C + (size_t)(bm + 32 * wm + 16 * mt + g) * 512 + bn + 64 * wn;
        float* Cp1 = Cp0 + (size_t)8 * 512;
#pragma unroll
        for (int nt = 0; nt < 8; ++nt) {
            *(float2*)(Cp0 + nt * 8 + 2 * c) = make_float2(acc[mt][nt][0], acc[mt][nt][1]);
            *(float2*)(Cp1 + nt * 8 + 2 * c) = make_float2(acc[mt][nt][2], acc[mt][nt][3]);
        }
    }
}

// ---------------------------------------------------------------------------
// SGEMM fp32 (FFMA2) — kept for the final Wo projection (accuracy margin).
// ---------------------------------------------------------------------------
__global__ __launch_bounds__(256) void sgemm_k512(
    const float* __restrict__ A, const float* __restrict__ Bw,
    float* __restrict__ C)
{
    __shared__ float Asf[8][128];
    __shared__ float Bsf[8][128];

    const int tid = threadIdx.x;
    const int tx = tid & 15;
    const int ty = tid >> 4;
    const int bn = blockIdx.x * 128;
    const int bm = blockIdx.y * 128;

    const int arow = tid >> 1;
    const int acol = (tid & 1) << 2;
    const int brow = tid >> 5;
    const int bcol = (tid & 31) << 2;

    const float* Ap = A + (size_t)(bm + arow) * 512 + acol;
    const float* Bp = Bw + (size_t)brow * 512 + bn + bcol;

    ull acc2[8][4];
#pragma unroll
    for (int i = 0; i < 8; ++i)
#pragma unroll
        for (int j = 0; j < 4; ++j) acc2[i][j] = 0ull;

    for (int k0 = 0; k0 < 512; k0 += 8) {
        float4 av = *(const float4*)Ap;  Ap += 8;
        float4 bv = *(const float4*)Bp;  Bp += 8 * 512;
        Asf[acol + 0][arow] = av.x;
        Asf[acol + 1][arow] = av.y;
        Asf[acol + 2][arow] = av.z;
        Asf[acol + 3][arow] = av.w;
        *(float4*)&Bsf[brow][bcol] = bv;
        __syncthreads();
#pragma unroll
        for (int kk = 0; kk < 8; ++kk) {
            float ar[8];
            *(float4*)(ar)     = *(const float4*)&Asf[kk][ty * 8];
            *(float4*)(ar + 4) = *(const float4*)&Asf[kk][ty * 8 + 4];
            ulonglong2 b01 = *(const ulonglong2*)&Bsf[kk][tx * 8];
            ulonglong2 b23 = *(const ulonglong2*)&Bsf[kk][tx * 8 + 4];
#pragma unroll
            for (int i = 0; i < 8; ++i) {
                ull ap = pk2(ar[i], ar[i]);
                acc2[i][0] = f2fma(ap, b01.x, acc2[i][0]);
                acc2[i][1] = f2fma(ap, b01.y, acc2[i][1]);
                acc2[i][2] = f2fma(ap, b23.x, acc2[i][2]);
                acc2[i][3] = f2fma(ap, b23.y, acc2[i][3]);
            }
        }
        __syncthreads();
    }

    float* Cp = C + (size_t)(bm + ty * 8) * 512 + bn + tx * 8;
#pragma unroll
    for (int i = 0; i < 8; ++i) {
        float c0, c1, c2, c3, c4, c5, c6, c7;
        upk(acc2[i][0], c0, c1); upk(acc2[i][1], c2, c3);
        upk(acc2[i][2], c4, c5); upk(acc2[i][3], c6, c7);
        *(float4*)(Cp + (size_t)i * 512)     = make_float4(c0, c1, c2, c3);
        *(float4*)(Cp + (size_t)i * 512 + 4) = make_float4(c4, c5, c6, c7);
    }
}

// ---------------------------------------------------------------------------
// Flash attention v5: tf32 mma, Bq=128 per CTA, 128 threads = 4 warps,
// each warp m32 x n64 (2 m16 tiles) -> 1.5 LDS per mma.
// smem (LDW=68, all fragment reads conflict-free):
//   Qs [128][68]  [q][d]
//   Ks [ 64][68]  K: [k][d]  then  Vt: [d][k]
//   Ps [128][68]  [q][k]
// Total = 320*68*4 = 87040 B -> 2 CTAs/SM.
// ---------------------------------------------------------------------------
#define LDW 68

__global__ void __launch_bounds__(128) flash_attn(
    const float* __restrict__ Q, const float* __restrict__ K,
    const float* __restrict__ V, const int* __restrict__ Mask,
    float* __restrict__ O)
{
    extern __shared__ u32 dsm[];
    u32* Qs = dsm;                   // [128][LDW]
    u32* Ks = dsm + 128 * LDW;       // [64][LDW] K then Vt
    u32* Ps = dsm + 192 * LDW;       // [128][LDW]

    const int tid  = threadIdx.x;
    const int lane = tid & 31;
    const int w    = tid >> 5;       // warp 0..3 -> q rows [32w, 32w+32)
    const int g    = lane >> 2;
    const int c    = lane & 3;
    const int q0 = blockIdx.x * 128;
    const int h  = blockIdx.y;
    const int b  = blockIdx.z;

    const int row  = tid >> 1;           // 0..63
    const int half = (tid & 1) * 32;

    // Load Q tile (128 rows) -> tf32 [q][d]
    {
        const float* qp = Q + (size_t)(b * Ss + q0 + tid) * HDv + h * 64;
#pragma unroll
        for (int i = 0; i < 16; ++i) {
            float4 v = *(const float4*)(qp + 4 * i);
            *(uint4*)&Qs[tid * LDW + 4 * i] =
                make_uint4(to_tf32(v.x), to_tf32(v.y), to_tf32(v.z), to_tf32(v.w));
        }
    }

    float m_[2][2], l_[2][2];
    float o[2][8][4];
#pragma unroll
    for (int mt = 0; mt < 2; ++mt) {
#pragma unroll
        for (int sb = 0; sb < 2; ++sb) { m_[mt][sb] = -CUDART_INF_F; l_[mt][sb] = 0.f; }
#pragma unroll
        for (int nt = 0; nt < 8; ++nt)
#pragma unroll
            for (int j = 0; j < 4; ++j) o[mt][nt][j] = 0.f;
    }

    // Mask row pointers: rows 32w+16mt+g and +8
    const int* mrow[2][2];
#pragma unroll
    for (int mt = 0; mt < 2; ++mt) {
        mrow[mt][0] = Mask + ((size_t)(b * Hh + h) * Ss + q0 + 32 * w + 16 * mt + g) * Ss;
        mrow[mt][1] = mrow[mt][0] + (size_t)8 * Ss;
    }

    for (int k0 = 0; k0 < Ss; k0 += 64) {
        __syncthreads();  // prior PV reads done (covers Q store, iter 0)

        // K tile -> tf32 [k][d]
        {
            const float* kp = K + (size_t)(b * Ss + k0 + row) * HDv + h * 64 + half;
#pragma unroll
            for (int i = 0; i < 8; ++i) {
                float4 v = *(const float4*)(kp + 4 * i);
                *(uint4*)&Ks[row * LDW + half + 4 * i] =
                    make_uint4(to_tf32(v.x), to_tf32(v.y), to_tf32(v.z), to_tf32(v.w));
            }
        }
        __syncthreads();

        // ---- S = Q K^T ----
        float s[2][8][4];
#pragma unroll
        for (int mt = 0; mt < 2; ++mt)
#pragma unroll
            for (int nt = 0; nt < 8; ++nt)
#pragma unroll
                for (int j = 0; j < 4; ++j) s[mt][nt][j] = 0.f;

#pragma unroll
        for (int ks = 0; ks < 8; ++ks) {
            u32 a[2][4];
#pragma unroll
            for (int mt = 0; mt < 2; ++mt) {
                int base = (32 * w + 16 * mt + g) * LDW + ks * 8 + c;
                a[mt][0] = Qs[base];
                a[mt][1] = Qs[base + 8 * LDW];
                a[mt][2] = Qs[base + 4];
                a[mt][3] = Qs[base + 8 * LDW + 4];
            }
#pragma unroll
            for (int nt = 0; nt < 8; ++nt) {
                u32 b0 = Ks[(nt * 8 + g) * LDW + ks * 8 + c];
                u32 b1 = Ks[(nt * 8 + g) * LDW + ks * 8 + c + 4];
#pragma unroll
                for (int mt = 0; mt < 2; ++mt)
                    mma_tf32(s[mt][nt][0], s[mt][nt][1], s[mt][nt][2], s[mt][nt][3],
                             a[mt][0], a[mt][1], a[mt][2], a[mt][3], b0, b1);
            }
        }

        // ---- online softmax per (mt, sub-row) ----
#pragma unroll
        for (int mt = 0; mt < 2; ++mt)
#pragma unroll
        for (int sb = 0; sb < 2; ++sb) {
            const int j0 = 2 * sb, j1 = 2 * sb + 1;
            int2 mr[8];
#pragma unroll
            for (int nt = 0; nt < 8; ++nt)
                mr[nt] = *(const int2*)(mrow[mt][sb] + k0 + nt * 8 + 2 * c);
            float mt_ = -CUDART_INF_F;
#pragma unroll
            for (int nt = 0; nt < 8; ++nt) {
                s[mt][nt][j0] = (mr[nt].x != 0) ? -1e10f : s[mt][nt][j0] * 0.125f;
                s[mt][nt][j1] = (mr[nt].y != 0) ? -1e10f : s[mt][nt][j1] * 0.125f;
                mt_ = fmaxf(mt_, fmaxf(s[mt][nt][j0], s[mt][nt][j1]));
            }
            mt_ = fmaxf(mt_, __shfl_xor_sync(0xffffffffu, mt_, 1));
            mt_ = fmaxf(mt_, __shfl_xor_sync(0xffffffffu, mt_, 2));
            float mnew = fmaxf(m_[mt][sb], mt_);
            float corr = __expf(m_[mt][sb] - mnew);
            m_[mt][sb] = mnew;
            float rs = 0.f;
            const int prow = (32 * w + 16 * mt + 8 * sb + g) * LDW;
#pragma unroll
            for (int nt = 0; nt < 8; ++nt) {
                float p0 = __expf(s[mt][nt][j0] - mnew);
                float p1 = __expf(s[mt][nt][j1] - mnew);
                rs += p0 + p1;
                *(uint2*)&Ps[prow + nt * 8 + 2 * c] = make_uint2(to_tf32(p0), to_tf32(p1));
                o[mt][nt][j0] *= corr;
                o[mt][nt][j1] *= corr;
            }
            rs += __shfl_xor_sync(0xffffffffu, rs, 1);
            rs += __shfl_xor_sync(0xffffffffu, rs, 2);
            l_[mt][sb] = l_[mt][sb] * corr + rs;
        }

        __syncthreads();  // QK reads of Ks done -> overwrite with Vt

        // V tile -> tf32 TRANSPOSED [d][k]
        {
            const float* vp = V + (size_t)(b * Ss + k0 + row) * HDv + h * 64 + half;
#pragma unroll
            for (int i = 0; i < 8; ++i) {
                float4 v = *(const float4*)(vp + 4 * i);
                int d = half + 4 * i;
                Ks[(d + 0) * LDW + row] = to_tf32(v.x);
                Ks[(d + 1) * LDW + row] = to_tf32(v.y);
                Ks[(d + 2) * LDW + row] = to_tf32(v.z);
                Ks[(d + 3) * LDW + row] = to_tf32(v.w);
            }
        }
        __syncthreads();  // Vt + P visible

        // ---- O += P V ----
#pragma unroll
        for (int kc = 0; kc < 8; ++kc) {
            u32 a[2][4];
#pragma unroll
            for (int mt = 0; mt < 2; ++mt) {
                int base = (32 * w + 16 * mt + g) * LDW + kc * 8 + c;
                a[mt][0] = Ps[base];
                a[mt][1] = Ps[base + 8 * LDW];
                a[mt][2] = Ps[base + 4];
                a[mt][3] = Ps[base + 8 * LDW + 4];
            }
#pragma unroll
            for (int nt = 0; nt < 8; ++nt) {
                u32 b0 = Ks[(nt * 8 + g) * LDW + kc * 8 + c];
                u32 b1 = Ks[(nt * 8 + g) * LDW + kc * 8 + c + 4];
#pragma unroll
                for (int mt = 0; mt < 2; ++mt)
                    mma_tf32(o[mt][nt][0], o[mt][nt][1], o[mt][nt][2], o[mt][nt][3],
                             a[mt][0], a[mt][1], a[mt][2], a[mt][3], b0, b1);
            }
        }
    }

    // normalize + write
#pragma unroll
    for (int mt = 0; mt < 2; ++mt) {
        const float inv0 = 1.f / l_[mt][0];
        const float inv1 = 1.f / l_[mt][1];
        float* op0 = O + (size_t)(b * Ss + q0 + 32 * w + 16 * mt + g) * HDv + h * 64;
        float* op1 = op0 + (size_t)8 * HDv;
#pragma unroll
        for (int nt = 0; nt < 8; ++nt) {
            *(float2*)(op0 + nt * 8 + 2 * c) =
                make_float2(o[mt][nt][0] * inv0, o[mt][nt][1] * inv0);
            *(float2*)(op1 + nt * 8 + 2 * c) =
                make_float2(o[mt][nt][2] * inv1, o[mt][nt][3] * inv1);
        }
    }
}

// ---------------------------------------------------------------------------
// Launch
// ---------------------------------------------------------------------------
extern "C" void kernel_launch(void* const* d_in, const int* in_sizes, int n_in,
                              void* d_out, int out_size)
{
    (void)in_sizes; (void)n_in; (void)out_size;
    const float* queries = (const float*)d_in[0];
    const float* keys    = (const float*)d_in[1];
    const float* values  = (const float*)d_in[2];
    const int*   mask    = (const int*)d_in[3];
    const float* Wq = (const float*)d_in[4];
    const float* Wk = (const float*)d_in[5];
    const float* Wv = (const float*)d_in[6];
    const float* Wo = (const float*)d_in[7];

    void *qp, *kp, *vp, *op;
    cudaGetSymbolAddress(&qp, Qg);
    cudaGetSymbolAddress(&kp, Kg);
    cudaGetSymbolAddress(&vp, Vg);
    cudaGetSymbolAddress(&op, Og);

    const int fsmem = 320 * LDW * 4;  // 87040
    cudaFuncSetAttribute(flash_attn,
                         cudaFuncAttributeMaxDynamicSharedMemorySize, fsmem);

    dim3 gg(512 / 128, (Bb * Ss) / 128);  // (4, 64)

    gemm_tf32_k512<<<gg, 256>>>(queries, Wq, (float*)qp);
    gemm_tf32_k512<<<gg, 256>>>(keys,    Wk, (float*)kp);
    gemm_tf32_k512<<<gg, 256>>>(values,  Wv, (float*)vp);

    flash_attn<<<dim3(Ss / 128, Hh, Bb), 128, fsmem>>>(
        (const float*)qp, (const float*)kp, (const float*)vp, mask, (float*)op);

    sgemm_k512<<<gg, 256>>>((const float*)op, Wo, (float*)d_out);
}

// round 7
// speedup vs baseline: 6.8122x; 1.0204x over previous
#include <cuda_runtime.h>
#include <math_constants.h>

// Problem constants
#define Bb 2
#define Ss 4096
#define Hh 8
#define HDv 512   // H*D (D=64)

typedef unsigned long long ull;
typedef unsigned int u32;

// Scratch (device globals; no allocation allowed)
__device__ float Qg[Bb * Ss * HDv];
__device__ float Kg[Bb * Ss * HDv];
__device__ float Vg[Bb * Ss * HDv];
__device__ float Og[Bb * Ss * HDv];

// ---- helpers --------------------------------------------------------------
__device__ __forceinline__ ull pk2(float a, float b) {
    ull r; asm("mov.b64 %0, {%1, %2};" : "=l"(r) : "f"(a), "f"(b)); return r;
}
__device__ __forceinline__ void upk(ull v, float& a, float& b) {
    asm("mov.b64 {%0, %1}, %2;" : "=f"(a), "=f"(b) : "l"(v));
}
__device__ __forceinline__ ull f2fma(ull a, ull b, ull c) {
    ull d; asm("fma.rn.f32x2 %0, %1, %2, %3;" : "=l"(d) : "l"(a), "l"(b), "l"(c));
    return d;
}
__device__ __forceinline__ u32 to_tf32(float f) {
    u32 r; asm("cvt.rna.tf32.f32 %0, %1;" : "=r"(r) : "f"(f)); return r;
}
__device__ __forceinline__ void mma_tf32(
    float& d0, float& d1, float& d2, float& d3,
    u32 a0, u32 a1, u32 a2, u32 a3, u32 b0, u32 b1)
{
    asm("mma.sync.aligned.m16n8k8.row.col.f32.tf32.tf32.f32 "
        "{%0,%1,%2,%3}, {%4,%5,%6,%7}, {%8,%9}, {%0,%1,%2,%3};"
        : "+f"(d0), "+f"(d1), "+f"(d2), "+f"(d3)
        : "r"(a0), "r"(a1), "r"(a2), "r"(a3), "r"(b0), "r"(b1));
}
// P-fragment permutation: accumulator layout (n=2c,2c+1) -> A layout (k=c,c+4)
__device__ __forceinline__ void pshuf(u32 p0, u32 p1, int srcA, int srcB, int e,
                                      u32& a_lo, u32& a_hi)
{
    u32 x00 = __shfl_sync(0xffffffffu, p0, srcA);
    u32 x01 = __shfl_sync(0xffffffffu, p1, srcA);
    u32 x10 = __shfl_sync(0xffffffffu, p0, srcB);
    u32 x11 = __shfl_sync(0xffffffffu, p1, srcB);
    a_lo = e ? x01 : x00;
    a_hi = e ? x11 : x10;
}

// ---------------------------------------------------------------------------
// tf32 GEMM for QKV projections (fused over grid.z): C = A[M,512] @ W[512,512].
// CTA 128x128, BK=32, 256 threads, warp m32 x n64.
// Epilogue stores tf32-ROUNDED floats (flash consumes raw bits, no in-loop cvt).
// ---------------------------------------------------------------------------
#define LDA 36
#define LDB 136

__global__ __launch_bounds__(256) void gemm_qkv_tf32(
    const float* __restrict__ A0, const float* __restrict__ A1,
    const float* __restrict__ A2,
    const float* __restrict__ W0, const float* __restrict__ W1,
    const float* __restrict__ W2,
    float* __restrict__ C0, float* __restrict__ C1, float* __restrict__ C2)
{
    __shared__ u32 As[128 * LDA];
    __shared__ u32 Bs[32 * LDB];

    const float* A; const float* Bw; float* C;
    if (blockIdx.z == 0)      { A = A0; Bw = W0; C = C0; }
    else if (blockIdx.z == 1) { A = A1; Bw = W1; C = C1; }
    else                      { A = A2; Bw = W2; C = C2; }

    const int tid  = threadIdx.x;
    const int lane = tid & 31;
    const int w    = tid >> 5;
    const int g    = lane >> 2;
    const int c    = lane & 3;
    const int wm   = w & 3;
    const int wn   = w >> 2;
    const int bn = blockIdx.x * 128;
    const int bm = blockIdx.y * 128;

    const int arow = tid >> 1;
    const int akg  = (tid & 1) * 16;
    const int brow = tid >> 3;
    const int bcg  = (tid & 7) * 16;

    float acc[2][8][4];
#pragma unroll
    for (int mt = 0; mt < 2; ++mt)
#pragma unroll
        for (int nt = 0; nt < 8; ++nt)
#pragma unroll
            for (int j = 0; j < 4; ++j) acc[mt][nt][j] = 0.f;

    for (int k0 = 0; k0 < 512; k0 += 32) {
        {
            const float* Ap = A + (size_t)(bm + arow) * 512 + k0 + akg;
#pragma unroll
            for (int i = 0; i < 4; ++i) {
                float4 v = *(const float4*)(Ap + 4 * i);
                *(uint4*)&As[arow * LDA + akg + 4 * i] =
                    make_uint4(to_tf32(v.x), to_tf32(v.y), to_tf32(v.z), to_tf32(v.w));
            }
        }
        {
            const float* Bp = Bw + (size_t)(k0 + brow) * 512 + bn + bcg;
#pragma unroll
            for (int i = 0; i < 4; ++i) {
                float4 v = *(const float4*)(Bp + 4 * i);
                *(uint4*)&Bs[brow * LDB + bcg + 4 * i] =
                    make_uint4(to_tf32(v.x), to_tf32(v.y), to_tf32(v.z), to_tf32(v.w));
            }
        }
        __syncthreads();

#pragma unroll
        for (int ks = 0; ks < 4; ++ks) {
            u32 a[2][4];
#pragma unroll
            for (int mt = 0; mt < 2; ++mt) {
                int base = (32 * wm + 16 * mt + g) * LDA + ks * 8 + c;
                a[mt][0] = As[base];
                a[mt][1] = As[base + 8 * LDA];
                a[mt][2] = As[base + 4];
                a[mt][3] = As[base + 8 * LDA + 4];
            }
#pragma unroll
            for (int nt = 0; nt < 8; ++nt) {
                u32 b0 = Bs[(ks * 8 + c)     * LDB + 64 * wn + nt * 8 + g];
                u32 b1 = Bs[(ks * 8 + c + 4) * LDB + 64 * wn + nt * 8 + g];
#pragma unroll
                for (int mt = 0; mt < 2; ++mt)
                    mma_tf32(acc[mt][nt][0], acc[mt][nt][1], acc[mt][nt][2], acc[mt][nt][3],
                             a[mt][0], a[mt][1], a[mt][2], a[mt][3], b0, b1);
            }
        }
        __syncthreads();
    }

#pragma unroll
    for (int mt = 0; mt < 2; ++mt) {
        float* Cp0 = C + (size_t)(bm + 32 * wm + 16 * mt + g) * 512 + bn + 64 * wn;
        float* Cp1 = Cp0 + (size_t)8 * 512;
#pragma unroll
        for (int nt = 0; nt < 8; ++nt) {
            *(uint2*)(Cp0 + nt * 8 + 2 * c) =
                make_uint2(to_tf32(acc[mt][nt][0]), to_tf32(acc[mt][nt][1]));
            *(uint2*)(Cp1 + nt * 8 + 2 * c) =
                make_uint2(to_tf32(acc[mt][nt][2]), to_tf32(acc[mt][nt][3]));
        }
    }
}

// ---------------------------------------------------------------------------
// SGEMM fp32 (FFMA2) — final Wo projection (accuracy margin).
// ---------------------------------------------------------------------------
__global__ __launch_bounds__(256) void sgemm_k512(
    const float* __restrict__ A, const float* __restrict__ Bw,
    float* __restrict__ C)
{
    __shared__ float Asf[8][128];
    __shared__ float Bsf[8][128];

    const int tid = threadIdx.x;
    const int tx = tid & 15;
    const int ty = tid >> 4;
    const int bn = blockIdx.x * 128;
    const int bm = blockIdx.y * 128;

    const int arow = tid >> 1;
    const int acol = (tid & 1) << 2;
    const int brow = tid >> 5;
    const int bcol = (tid & 31) << 2;

    const float* Ap = A + (size_t)(bm + arow) * 512 + acol;
    const float* Bp = Bw + (size_t)brow * 512 + bn + bcol;

    ull acc2[8][4];
#pragma unroll
    for (int i = 0; i < 8; ++i)
#pragma unroll
        for (int j = 0; j < 4; ++j) acc2[i][j] = 0ull;

    for (int k0 = 0; k0 < 512; k0 += 8) {
        float4 av = *(const float4*)Ap;  Ap += 8;
        float4 bv = *(const float4*)Bp;  Bp += 8 * 512;
        Asf[acol + 0][arow] = av.x;
        Asf[acol + 1][arow] = av.y;
        Asf[acol + 2][arow] = av.z;
        Asf[acol + 3][arow] = av.w;
        *(float4*)&Bsf[brow][bcol] = bv;
        __syncthreads();
#pragma unroll
        for (int kk = 0; kk < 8; ++kk) {
            float ar[8];
            *(float4*)(ar)     = *(const float4*)&Asf[kk][ty * 8];
            *(float4*)(ar + 4) = *(const float4*)&Asf[kk][ty * 8 + 4];
            ulonglong2 b01 = *(const ulonglong2*)&Bsf[kk][tx * 8];
            ulonglong2 b23 = *(const ulonglong2*)&Bsf[kk][tx * 8 + 4];
#pragma unroll
            for (int i = 0; i < 8; ++i) {
                ull ap = pk2(ar[i], ar[i]);
                acc2[i][0] = f2fma(ap, b01.x, acc2[i][0]);
                acc2[i][1] = f2fma(ap, b01.y, acc2[i][1]);
                acc2[i][2] = f2fma(ap, b23.x, acc2[i][2]);
                acc2[i][3] = f2fma(ap, b23.y, acc2[i][3]);
            }
        }
        __syncthreads();
    }

    float* Cp = C + (size_t)(bm + ty * 8) * 512 + bn + tx * 8;
#pragma unroll
    for (int i = 0; i < 8; ++i) {
        float c0, c1, c2, c3, c4, c5, c6, c7;
        upk(acc2[i][0], c0, c1); upk(acc2[i][1], c2, c3);
        upk(acc2[i][2], c4, c5); upk(acc2[i][3], c6, c7);
        *(float4*)(Cp + (size_t)i * 512)     = make_float4(c0, c1, c2, c3);
        *(float4*)(Cp + (size_t)i * 512 + 4) = make_float4(c4, c5, c6, c7);
    }
}

// ---------------------------------------------------------------------------
// Flash attention v6: tf32 mma, Bq=128, 128 threads = 4 warps m32n64.
// P stays in REGISTERS (shfl permutation into A-fragment layout) — no Ps smem.
// Inputs pre-rounded to tf32 by the projection epilogue — no in-loop cvt.
// smem 69632 B: Qs[128][68] | Ks[64][68] ([k][d]) | Vs[64][68] (Vt [d][k])
// 2 barriers per k-tile. 3 CTAs/SM.
// ---------------------------------------------------------------------------
#define LDW 68

__global__ void __launch_bounds__(128, 3) flash_attn(
    const float* __restrict__ Q, const float* __restrict__ K,
    const float* __restrict__ V, const int* __restrict__ Mask,
    float* __restrict__ O)
{
    extern __shared__ u32 dsm[];
    u32* Qs = dsm;                   // [128][LDW] [q][d]
    u32* Ks = dsm + 128 * LDW;       // [64][LDW]  [k][d]
    u32* Vs = dsm + 192 * LDW;       // [64][LDW]  Vt [d][k]

    const int tid  = threadIdx.x;
    const int lane = tid & 31;
    const int w    = tid >> 5;
    const int g    = lane >> 2;
    const int c    = lane & 3;
    const int q0 = blockIdx.x * 128;
    const int h  = blockIdx.y;
    const int b  = blockIdx.z;

    const int row  = tid >> 1;
    const int half = (tid & 1) * 32;

    const int srcA = (lane & 0x1C) | (c >> 1);
    const int srcB = srcA + 2;
    const int e    = c & 1;

    // Q tile: raw bit copy (already tf32-valued)
    {
        const float* qp = Q + (size_t)(b * Ss + q0 + tid) * HDv + h * 64;
#pragma unroll
        for (int i = 0; i < 16; ++i)
            *(uint4*)&Qs[tid * LDW + 4 * i] = *(const uint4*)(qp + 4 * i);
    }

    float m_[2][2], l_[2][2];
    float o[2][8][4];
#pragma unroll
    for (int mt = 0; mt < 2; ++mt) {
#pragma unroll
        for (int sb = 0; sb < 2; ++sb) { m_[mt][sb] = -CUDART_INF_F; l_[mt][sb] = 0.f; }
#pragma unroll
        for (int nt = 0; nt < 8; ++nt)
#pragma unroll
            for (int j = 0; j < 4; ++j) o[mt][nt][j] = 0.f;
    }

    const int* mrow[2][2];
#pragma unroll
    for (int mt = 0; mt < 2; ++mt) {
        mrow[mt][0] = Mask + ((size_t)(b * Hh + h) * Ss + q0 + 32 * w + 16 * mt + g) * Ss;
        mrow[mt][1] = mrow[mt][0] + (size_t)8 * Ss;
    }

    for (int k0 = 0; k0 < Ss; k0 += 64) {
        __syncthreads();  // Ks/Vs free (prev QK+PV done); covers Q store iter 0

        // K natural [k][d] + V transposed [d][k] (raw bit copies)
        {
            const float* kp = K + (size_t)(b * Ss + k0 + row) * HDv + h * 64 + half;
            const float* vp = V + (size_t)(b * Ss + k0 + row) * HDv + h * 64 + half;
#pragma unroll
            for (int i = 0; i < 8; ++i)
                *(uint4*)&Ks[row * LDW + half + 4 * i] = *(const uint4*)(kp + 4 * i);
#pragma unroll
            for (int i = 0; i < 8; ++i) {
                uint4 v = *(const uint4*)(vp + 4 * i);
                int d = half + 4 * i;
                Vs[(d + 0) * LDW + row] = v.x;
                Vs[(d + 1) * LDW + row] = v.y;
                Vs[(d + 2) * LDW + row] = v.z;
                Vs[(d + 3) * LDW + row] = v.w;
            }
        }
        __syncthreads();  // tiles visible

        // ---- S = Q K^T ----
        float s[2][8][4];
#pragma unroll
        for (int mt = 0; mt < 2; ++mt)
#pragma unroll
            for (int nt = 0; nt < 8; ++nt)
#pragma unroll
                for (int j = 0; j < 4; ++j) s[mt][nt][j] = 0.f;

#pragma unroll
        for (int ks = 0; ks < 8; ++ks) {
            u32 a[2][4];
#pragma unroll
            for (int mt = 0; mt < 2; ++mt) {
                int base = (32 * w + 16 * mt + g) * LDW + ks * 8 + c;
                a[mt][0] = Qs[base];
                a[mt][1] = Qs[base + 8 * LDW];
                a[mt][2] = Qs[base + 4];
                a[mt][3] = Qs[base + 8 * LDW + 4];
            }
#pragma unroll
            for (int nt = 0; nt < 8; ++nt) {
                u32 b0 = Ks[(nt * 8 + g) * LDW + ks * 8 + c];
                u32 b1 = Ks[(nt * 8 + g) * LDW + ks * 8 + c + 4];
#pragma unroll
                for (int mt = 0; mt < 2; ++mt)
                    mma_tf32(s[mt][nt][0], s[mt][nt][1], s[mt][nt][2], s[mt][nt][3],
                             a[mt][0], a[mt][1], a[mt][2], a[mt][3], b0, b1);
            }
        }

        // ---- online softmax (P kept in s[][][] as rounded tf32 bits) ----
#pragma unroll
        for (int mt = 0; mt < 2; ++mt)
#pragma unroll
        for (int sb = 0; sb < 2; ++sb) {
            const int j0 = 2 * sb, j1 = 2 * sb + 1;
            int2 mr[8];
#pragma unroll
            for (int nt = 0; nt < 8; ++nt)
                mr[nt] = *(const int2*)(mrow[mt][sb] + k0 + nt * 8 + 2 * c);
            float mt_ = -CUDART_INF_F;
#pragma unroll
            for (int nt = 0; nt < 8; ++nt) {
                s[mt][nt][j0] = (mr[nt].x != 0) ? -1e10f : s[mt][nt][j0] * 0.125f;
                s[mt][nt][j1] = (mr[nt].y != 0) ? -1e10f : s[mt][nt][j1] * 0.125f;
                mt_ = fmaxf(mt_, fmaxf(s[mt][nt][j0], s[mt][nt][j1]));
            }
            mt_ = fmaxf(mt_, __shfl_xor_sync(0xffffffffu, mt_, 1));
            mt_ = fmaxf(mt_, __shfl_xor_sync(0xffffffffu, mt_, 2));
            float mnew = fmaxf(m_[mt][sb], mt_);
            float corr = __expf(m_[mt][sb] - mnew);
            m_[mt][sb] = mnew;
            float rs = 0.f;
#pragma unroll
            for (int nt = 0; nt < 8; ++nt) {
                float p0 = __uint_as_float(to_tf32(__expf(s[mt][nt][j0] - mnew)));
                float p1 = __uint_as_float(to_tf32(__expf(s[mt][nt][j1] - mnew)));
                rs += p0 + p1;
                s[mt][nt][j0] = p0;
                s[mt][nt][j1] = p1;
                o[mt][nt][j0] *= corr;
                o[mt][nt][j1] *= corr;
            }
            rs += __shfl_xor_sync(0xffffffffu, rs, 1);
            rs += __shfl_xor_sync(0xffffffffu, rs, 2);
            l_[mt][sb] = l_[mt][sb] * corr + rs;
        }

        // ---- O += P V  (A-fragments via shfl from s; B from Vs) ----
#pragma unroll
        for (int kc = 0; kc < 8; ++kc) {
            u32 a[2][4];
#pragma unroll
            for (int mt = 0; mt < 2; ++mt) {
                pshuf(__float_as_uint(s[mt][kc][0]), __float_as_uint(s[mt][kc][1]),
                      srcA, srcB, e, a[mt][0], a[mt][2]);
                pshuf(__float_as_uint(s[mt][kc][2]), __float_as_uint(s[mt][kc][3]),
                      srcA, srcB, e, a[mt][1], a[mt][3]);
            }
#pragma unroll
            for (int nt = 0; nt < 8; ++nt) {
                u32 b0 = Vs[(nt * 8 + g) * LDW + kc * 8 + c];
                u32 b1 = Vs[(nt * 8 + g) * LDW + kc * 8 + c + 4];
#pragma unroll
                for (int mt = 0; mt < 2; ++mt)
                    mma_tf32(o[mt][nt][0], o[mt][nt][1], o[mt][nt][2], o[mt][nt][3],
                             a[mt][0], a[mt][1], a[mt][2], a[mt][3], b0, b1);
            }
        }
    }

    // normalize + write
#pragma unroll
    for (int mt = 0; mt < 2; ++mt) {
        const float inv0 = 1.f / l_[mt][0];
        const float inv1 = 1.f / l_[mt][1];
        float* op0 = O + (size_t)(b * Ss + q0 + 32 * w + 16 * mt + g) * HDv + h * 64;
        float* op1 = op0 + (size_t)8 * HDv;
#pragma unroll
        for (int nt = 0; nt < 8; ++nt) {
            *(float2*)(op0 + nt * 8 + 2 * c) =
                make_float2(o[mt][nt][0] * inv0, o[mt][nt][1] * inv0);
            *(float2*)(op1 + nt * 8 + 2 * c) =
                make_float2(o[mt][nt][2] * inv1, o[mt][nt][3] * inv1);
        }
    }
}

// ---------------------------------------------------------------------------
// Launch
// ---------------------------------------------------------------------------
extern "C" void kernel_launch(void* const* d_in, const int* in_sizes, int n_in,
                              void* d_out, int out_size)
{
    (void)in_sizes; (void)n_in; (void)out_size;
    const float* queries = (const float*)d_in[0];
    const float* keys    = (const float*)d_in[1];
    const float* values  = (const float*)d_in[2];
    const int*   mask    = (const int*)d_in[3];
    const float* Wq = (const float*)d_in[4];
    const float* Wk = (const float*)d_in[5];
    const float* Wv = (const float*)d_in[6];
    const float* Wo = (const float*)d_in[7];

    void *qp, *kp, *vp, *op;
    cudaGetSymbolAddress(&qp, Qg);
    cudaGetSymbolAddress(&kp, Kg);
    cudaGetSymbolAddress(&vp, Vg);
    cudaGetSymbolAddress(&op, Og);

    const int fsmem = 256 * LDW * 4;  // 69632
    cudaFuncSetAttribute(flash_attn,
                         cudaFuncAttributeMaxDynamicSharedMemorySize, fsmem);

    dim3 gg(512 / 128, (Bb * Ss) / 128);        // (4, 64)
    dim3 gq(512 / 128, (Bb * Ss) / 128, 3);     // fused QKV

    gemm_qkv_tf32<<<gq, 256>>>(queries, keys, values, Wq, Wk, Wv,
                               (float*)qp, (float*)kp, (float*)vp);

    flash_attn<<<dim3(Ss / 128, Hh, Bb), 128, fsmem>>>(
        (const float*)qp, (const float*)kp, (const float*)vp, mask, (float*)op);

    sgemm_k512<<<gg, 256>>>((const float*)op, Wo, (float*)d_out);
}